// round 11
// baseline (speedup 1.0000x reference)
#include <cuda_runtime.h>
#include <cuda_fp16.h>
#include <cstdint>
#include <cstddef>

// Correlation as band-Gram fp16 mma.sync GEMM (m16n8k16, fp32 accumulate).
// Pass 1: reformat d2 -> g_B, per (b,row): [par][t:7][kp2:3][lane:32][e:4]
//   e in {0,1}: kp=2*kp2 regs (b0,b1); e in {2,3}: kp=2*kp2+1 regs.
//   word = half2{ d2[c], d2[c+1] }, c = 16*kp + 2q + 8*(e&1), x = 16t+2g-4+par.
// Pass 2: block = (y-pair, b), 384 thr, 2 blocks/SM. Rows y0, y0+2 share B
//   rows; loop s over 23 union steps; warp (h,m,par) computes i = s-h.
//   B rows via cp.async distance-1 double buffer; result staged in OUTPUT
//   coords [j:21][x:96] (stride 100) -> writeout is contiguous LDS.128.

#define NT   384
#define XROW 100                           // stage row stride (floats)
#define STAGE_H (21 * XROW)                // 2100 floats per y-half
#define STAGE_FLOATS (2 * STAGE_H)         // 4200 per buffer
#define B_U32   5376                       // u32 words per row (2 par x 2688)
#define B_BYTES 21504
#define NBUF    2
#define STAGE_OFF_B (NBUF * B_BYTES)       // 43008
#define SMEM_BYTES (STAGE_OFF_B + 2 * STAGE_FLOATS * 4)   // 76608 -> 2 blk/SM

#define GB_N 2752512                       // 8*64*5376
__device__ uint32_t g_B[GB_N];

__device__ __forceinline__ uint32_t packh2(float a, float b) {
    __half2 h = __floats2half2_rn(a, b);
    return *(uint32_t*)&h;
}
__device__ __forceinline__ uint32_t s2u(const void* p) {
    uint32_t a;
    asm("{ .reg .u64 t; cvta.to.shared.u64 t, %1; cvt.u32.u64 %0, t; }"
        : "=r"(a) : "l"(p));
    return a;
}
__device__ __forceinline__ void mma16(float* c, const uint32_t* a,
                                      uint32_t b0, uint32_t b1) {
    asm volatile(
        "mma.sync.aligned.m16n8k16.row.col.f32.f16.f16.f32 "
        "{%0,%1,%2,%3}, {%4,%5,%6,%7}, {%8,%9}, {%0,%1,%2,%3};"
        : "+f"(c[0]), "+f"(c[1]), "+f"(c[2]), "+f"(c[3])
        : "r"(a[0]), "r"(a[1]), "r"(a[2]), "r"(a[3]), "r"(b0), "r"(b1));
}

// ---------------- pass 1: reformat d2 -> g_B (smem transpose) --------------
__global__ void __launch_bounds__(256) reformat(const float* __restrict__ d2) {
    __shared__ float t[96 * 100];
    const int td  = threadIdx.x;
    const int row = blockIdx.x & 63;
    const int b   = blockIdx.x >> 6;

    const float* src = d2 + ((size_t)b * 96 * 64 + row) * 96;
    #pragma unroll
    for (int it = 0; it < 9; ++it) {
        int lin = it * 256 + td;
        int c = lin / 24, xq = lin - c * 24;
        float4 v = *(const float4*)(src + (size_t)c * 6144 + 4 * xq);
        *(float4*)(t + c * 100 + 4 * xq) = v;
    }
    __syncthreads();

    uint32_t* dst = g_B + (size_t)(b * 64 + row) * B_U32;
    #pragma unroll
    for (int it = 0; it < 21; ++it) {      // 5376 words
        int lin = it * 256 + td;
        int e = lin & 3;
        int l = (lin >> 2) & 31;
        int blk = lin >> 7;                // ((par*7 + tt)*3 + kp2)
        int kp2 = blk % 3, pt = blk / 3;
        int tt = pt % 7, par = pt / 7;
        int g = l >> 2, q = l & 3;
        int kp = 2 * kp2 + (e >> 1);
        int c = 16 * kp + 2 * q + 8 * (e & 1);
        int x = 16 * tt + 2 * g - 4 + par;
        float v0 = 0.f, v1 = 0.f;
        if ((unsigned)x < 96u) { v0 = t[c * 100 + x]; v1 = t[(c + 1) * 100 + x]; }
        dst[lin] = packh2(v0, v1);
    }
}

// ---------------- pass 2: paired-y GEMM ----------------
__device__ __forceinline__ void writeout_half(
    float* __restrict__ out, const float* __restrict__ stb,
    int b, int yv, int iv, bool vv, float sc, int td)
{
    if ((unsigned)iv >= 21u) return;
    float* ob = out + ((size_t)(b * 441 + iv * 21) * 64 + yv) * 96;
    #pragma unroll
    for (int rep = 0; rep < 2; ++rep) {
        int uu = td + NT * rep;
        if (uu < 504) {
            int j = uu / 24, xq = uu - j * 24;
            float4 o;
            if (vv) {
                float4 v = *(const float4*)(stb + j * XROW + 4 * xq);
                o = make_float4(v.x * sc, v.y * sc, v.z * sc, v.w * sc);
            } else {
                o = make_float4(0.f, 0.f, 0.f, 0.f);
            }
            __stcs((float4*)(ob + (size_t)j * 6144 + 4 * xq), o);
        }
    }
}

__global__ void __launch_bounds__(NT, 2) corr_mma(
    const float* __restrict__ d1,
    const float* __restrict__ s1, const float* __restrict__ s2,
    const float* __restrict__ osc, float* __restrict__ out)
{
    extern __shared__ char smc[];
    uint32_t* bsm = (uint32_t*)smc;                  // [2][B_U32]
    float* stage = (float*)(smc + STAGE_OFF_B);      // [2 buf][2h][21 j][XROW]
    const uint32_t bsm_u = s2u(smc);

    const int td = threadIdx.x;
    const int w = td >> 5, l = td & 31;
    const int h = w / 6, w6 = w % 6, m = w6 >> 1, par = w6 & 1;
    const int g = l >> 2, q = l & 3;
    const int t0 = (m == 0) ? 0 : ((m == 1) ? 1 : 3);
    const int nt = (m == 1) ? 5 : 4;

    const int yp = blockIdx.x;
    const int y0 = 4 * (yp >> 1) + (yp & 1);
    const int b = blockIdx.y;
    const int y = y0 + 2 * h;

    // zero both stage buffers (unwritten (j,x) slots = OOB x' -> must read 0)
    {
        float4 z = make_float4(0.f, 0.f, 0.f, 0.f);
        float4* p = (float4*)stage;
        for (int i = td; i < 2 * STAGE_FLOATS / 4; i += NT) p[i] = z;
    }

    // A frags (fp16, register-resident, per warp's y)
    uint32_t A[6][4];
    {
        int xg = 2 * (16 * m + g) + par;
        int xg8 = xg + 16;
        const float* p0 = d1 + ((size_t)(b * 96) * 64 + y) * 96;
        #pragma unroll
        for (int kp = 0; kp < 6; ++kp) {
            const float* pc = p0 + (size_t)(16 * kp + 2 * q) * 6144;
            A[kp][0] = packh2(pc[xg],             pc[6144 + xg]);
            A[kp][1] = packh2(pc[xg8],            pc[6144 + xg8]);
            A[kp][2] = packh2(pc[8 * 6144 + xg],  pc[9 * 6144 + xg]);
            A[kp][3] = packh2(pc[8 * 6144 + xg8], pc[9 * 6144 + xg8]);
        }
    }

    float acc[5][4];
    #pragma unroll
    for (int tt = 0; tt < 5; ++tt)
        #pragma unroll
        for (int e = 0; e < 4; ++e) acc[tt][e] = 0.f;

    const float sc = s1[0] * s2[0] / (96.0f * osc[0]);
    const size_t gbase = (size_t)(b * 64) * B_U32;
    const int xbase = 32 * m + 2 * g + par;          // x of xp row 16m+g

    auto prefetch = [&](int s_idx, int bi) {
        int row = y0 - 20 + 2 * s_idx;
        if (s_idx <= 21 && (unsigned)row < 64u) {
            const char* gp = (const char*)(g_B + gbase + (size_t)row * B_U32);
            uint32_t sa = bsm_u + bi * B_BYTES;
            #pragma unroll
            for (int u = 0; u < 4; ++u) {
                int idx = u * NT + td;
                if (idx < 1344)
                    asm volatile("cp.async.cg.shared.global [%0], [%1], 16;"
                                 :: "r"(sa + idx * 16), "l"(gp + idx * 16)
                                 : "memory");
            }
        }
        asm volatile("cp.async.commit_group;" ::: "memory");
    };

    prefetch(0, 0);

    for (int s = 0; s < 23; ++s) {
        asm volatile("cp.async.wait_group 0;" ::: "memory");
        __syncthreads();

        // P(s+1) into buffer (s+1)&1: last read in compute(s-1), retired above.
        prefetch(s + 1, (s + 1) & 1);

        // ---- writeout of stage(s-1) from the other stage buffer ----
        if (s >= 1) {
            const float* stb = stage + ((s - 1) & 1) * STAGE_FLOATS;
            bool vp = (unsigned)(y0 + 2 * (s - 1) - 20) < 64u;
            writeout_half(out, stb,           b, y0,     s - 1, vp, sc, td);
            writeout_half(out, stb + STAGE_H, b, y0 + 2, s - 2, vp, sc, td);
        }

        // ---- compute(s) into stage buffer s&1 ----
        const int r = y0 + 2 * s - 20;
        const bool vr = (unsigned)r < 64u;
        const int i = s - h;
        if (s <= 21 && vr && (unsigned)i < 21u) {
            const uint32_t* bb = bsm + (s & 1) * B_U32 + par * 2688
                                 + t0 * 384 + 4 * l;
            #pragma unroll
            for (int kp2 = 0; kp2 < 3; ++kp2) {
                #pragma unroll
                for (int tt = 0; tt < 5; ++tt) {
                    if (tt < nt) {
                        uint4 v = *(const uint4*)(bb + tt * 384 + kp2 * 128);
                        mma16(acc[tt], A[2 * kp2],     v.x, v.y);
                        mma16(acc[tt], A[2 * kp2 + 1], v.z, v.w);
                    }
                }
            }
            // stage accs in output coords: stage[j][x]
            float* stg = stage + (s & 1) * STAGE_FLOATS + h * STAGE_H;
            #pragma unroll
            for (int tt = 0; tt < 5; ++tt) {
                if (tt < nt) {
                    int j0 = 8 * (t0 + tt + 1) + 2 * q - 16 * m - g;
                    int j1 = j0 - 8;
                    if ((unsigned)j0 < 21u)       stg[j0 * XROW + xbase]            = acc[tt][0];
                    if ((unsigned)(j0 + 1) < 21u) stg[(j0 + 1) * XROW + xbase]      = acc[tt][1];
                    if ((unsigned)j1 < 21u)       stg[j1 * XROW + xbase + 16]       = acc[tt][2];
                    if ((unsigned)(j1 + 1) < 21u) stg[(j1 + 1) * XROW + xbase + 16] = acc[tt][3];
                    acc[tt][0] = acc[tt][1] = acc[tt][2] = acc[tt][3] = 0.f;
                }
            }
        }
    }
}

extern "C" void kernel_launch(void* const* d_in, const int* in_sizes, int n_in,
                              void* d_out, int out_size) {
    const float* data1     = (const float*)d_in[0];
    const float* data2     = (const float*)d_in[1];
    const float* scale1    = (const float*)d_in[2];
    const float* scale2    = (const float*)d_in[3];
    /* d_in[4] = inter_scale, unused by the reference math */
    const float* out_scale = (const float*)d_in[5];

    reformat<<<512, 256>>>(data2);

    cudaFuncSetAttribute(corr_mma, cudaFuncAttributeMaxDynamicSharedMemorySize,
                         SMEM_BYTES);
    dim3 grid(32, 8);   // (y-pair, b)
    corr_mma<<<grid, NT, SMEM_BYTES>>>(data1, scale1, scale2, out_scale,
                                       (float*)d_out);
}